// round 10
// baseline (speedup 1.0000x reference)
#include <cuda_runtime.h>
#include <cuda_bf16.h>
#include <cstddef>
#include <cstdint>

#define NV 100000
#define NF 200000
#define DD 512

// ---------------- scratch (static device arrays; no allocation) ----------------
__device__ __align__(256) __nv_bfloat16 g_fhi[(size_t)NV * DD];
__device__ __align__(256) __nv_bfloat16 g_flo[(size_t)NV * DD];
__device__ __align__(256) float         g_Y[(size_t)NV * DD];
__device__ __align__(256) __nv_bfloat16 g_h1hi[(size_t)NF * DD];
__device__ __align__(256) __nv_bfloat16 g_h1lo[(size_t)NF * DD];
__device__ __align__(256) __nv_bfloat16 g_h2hi[(size_t)NF * DD];
__device__ __align__(256) __nv_bfloat16 g_h2lo[(size_t)NF * DD];
__device__ __align__(256) float         g_h3[(size_t)NF * 256];
__device__ __align__(256) __nv_bfloat16 g_B1hi[DD * DD];
__device__ __align__(256) __nv_bfloat16 g_B1lo[DD * DD];
__device__ __align__(256) __nv_bfloat16 g_B2hi[DD * DD];
__device__ __align__(256) __nv_bfloat16 g_B2lo[DD * DD];
__device__ __align__(256) __nv_bfloat16 g_B3hi[256 * DD];
__device__ __align__(256) __nv_bfloat16 g_B3lo[256 * DD];
__device__ __align__(256) float         g_sum[(size_t)NV * 3];
__device__ __align__(256) float         g_cnt[NV];

// ---------------- HMMA GEMM helpers ----------------
#define CP16(dst, src) \
    asm volatile("cp.async.cg.shared.global.L2::128B [%0], [%1], 16;" :: "r"(dst), "l"(src) : "memory")

__device__ __forceinline__ void ldm_x4(uint32_t& r0, uint32_t& r1, uint32_t& r2, uint32_t& r3,
                                       uint32_t addr) {
    asm volatile("ldmatrix.sync.aligned.m8n8.x4.shared.b16 {%0,%1,%2,%3}, [%4];"
                 : "=r"(r0), "=r"(r1), "=r"(r2), "=r"(r3) : "r"(addr));
}

__device__ __forceinline__ void mma_bf16(float* c, const uint32_t* a, uint32_t b0, uint32_t b1) {
    asm volatile("mma.sync.aligned.m16n8k16.row.col.f32.bf16.bf16.f32 "
                 "{%0,%1,%2,%3}, {%4,%5,%6,%7}, {%8,%9}, {%0,%1,%2,%3};"
                 : "+f"(c[0]), "+f"(c[1]), "+f"(c[2]), "+f"(c[3])
                 : "r"(a[0]), "r"(a[1]), "r"(a[2]), "r"(a[3]), "r"(b0), "r"(b1));
}

// SW128 swizzle: 128B rows, 16B chunk c in 0..7, slot = c ^ (row & 7).
__device__ __forceinline__ uint32_t swz128(uint32_t base, int row, int chunk) {
    return base + (uint32_t)row * 128u + (uint32_t)((chunk ^ (row & 7)) << 4);
}

// ---------------- persistent HMMA GEMM: C = [relu]( (Ahi+Alo)@(Bhi+Blo)^T [+bias] ) -------
// A: [M,K] row-major bf16 hi/lo.  B: [N,K] row-major bf16 hi/lo (W transposed).
// Block tile 128x64, 256 threads = 8 warps (4 M x 2 N), warp tile 32x32.
// K-chunk 64 (128B rows, SW128), 2-stage cp.async ring, frag double-buffer across ks.
// PERSISTENT: grid = 296 CTAs loop over tiles; next tile's stage-0 issued during the
// last K-chunk so its DRAM latency hides under compute + epilogue.
// Stage: Ah@0(16K), Al@16K, Bh@32K(8K), Bl@40K; stage 48KB; 2 stages 96KB => 2 CTAs/SM.
#define A_MATB 16384u
#define B_BASE 32768u
#define B_MATB 8192u
#define STAGEB 49152u
#define GEMM_SMEM_BYTES (2 * STAGEB)
#define GEMM_GRID 296

template<bool RELU, bool BIAS, bool OUTF32>
__global__ void __launch_bounds__(256, 2)
gemm_mma(const __nv_bfloat16* __restrict__ Ahi, const __nv_bfloat16* __restrict__ Alo,
         const __nv_bfloat16* __restrict__ Bhi, const __nv_bfloat16* __restrict__ Blo,
         const float* __restrict__ bias,
         float* __restrict__ Cf, __nv_bfloat16* __restrict__ Chi, __nv_bfloat16* __restrict__ Clo,
         int M, int N, int K)
{
    extern __shared__ __align__(256) char smem[];
    const uint32_t sbase = (uint32_t)__cvta_generic_to_shared(smem);
    const int tid = threadIdx.x;
    const int wid = tid >> 5;
    const int lid = tid & 31;
    const int wm = (wid & 3) * 32;
    const int wn = (wid >> 2) * 32;
    const int NK = K >> 6;               // K-chunks of 64 (8 for K=512)

    const int ntn = N >> 6;              // N-tiles of 64
    const int ntm = (M + 127) >> 7;      // M-tiles of 128
    const int ntiles = ntm * ntn;

    // ldmatrix lane-address components
    const int a_row = ((lid >> 3) & 1) * 8 + (lid & 7);
    const int a_co  = lid >> 4;
    const int b_row = (lid >> 4) * 8 + (lid & 7);
    const int b_co  = (lid >> 3) & 1;

    auto load_stage = [&](int bm, int bn, int kt, int buf) {
        const uint32_t sb = sbase + (uint32_t)buf * STAGEB;
        const int kc = kt << 6;
        #pragma unroll
        for (int i = 0; i < 4; i++) {
            const int idx = tid + i * 256;      // 0..1023
            const int r = idx >> 3, c = idx & 7;
            int gr = bm + r; if (gr >= M) gr = M - 1;
            const size_t aoff = (size_t)gr * K + kc + c * 8;
            const uint32_t da = swz128(sb, r, c);
            CP16(da,          Ahi + aoff);
            CP16(da + A_MATB, Alo + aoff);
        }
        #pragma unroll
        for (int i = 0; i < 2; i++) {
            const int idx = tid + i * 256;      // 0..511
            const int r = idx >> 3, c = idx & 7;
            const size_t boff = (size_t)(bn + r) * K + kc + c * 8;
            const uint32_t db = swz128(sb + B_BASE, r, c);
            CP16(db,          Bhi + boff);
            CP16(db + B_MATB, Blo + boff);
        }
        asm volatile("cp.async.commit_group;" ::: "memory");
    };

    uint32_t ah[2][2][4], al[2][2][4], bh[2][2][4], bl[2][2][4];

    auto load_frags = [&](uint32_t sb, int slot, int ks) {
        #pragma unroll
        for (int mi = 0; mi < 2; mi++) {
            const int row = wm + mi * 16 + a_row;
            const int chunk = (ks >> 3) + a_co;
            const uint32_t ra = swz128(sb, row, chunk);
            ldm_x4(ah[slot][mi][0], ah[slot][mi][1], ah[slot][mi][2], ah[slot][mi][3], ra);
            ldm_x4(al[slot][mi][0], al[slot][mi][1], al[slot][mi][2], al[slot][mi][3], ra + A_MATB);
        }
        #pragma unroll
        for (int nt = 0; nt < 2; nt++) {
            const int row = wn + nt * 16 + b_row;
            const int chunk = (ks >> 3) + b_co;
            const uint32_t rb = swz128(sb + B_BASE, row, chunk);
            ldm_x4(bh[slot][nt][0], bh[slot][nt][1], bh[slot][nt][2], bh[slot][nt][3], rb);
            ldm_x4(bl[slot][nt][0], bl[slot][nt][1], bl[slot][nt][2], bl[slot][nt][3], rb + B_MATB);
        }
    };

    const int t0 = blockIdx.x;
    if (t0 >= ntiles) return;

    // prologue: first tile's stage 0
    {
        const int bm = (t0 / ntn) << 7;
        const int bn = (t0 % ntn) << 6;
        load_stage(bm, bn, 0, 0);
    }

    for (int t = t0; t < ntiles; t += GEMM_GRID) {
        const int bm = (t / ntn) << 7;
        const int bn = (t % ntn) << 6;
        const int tnext = t + GEMM_GRID;

        float acc[2][4][4];
        #pragma unroll
        for (int i = 0; i < 2; i++)
            #pragma unroll
            for (int j = 0; j < 4; j++)
                #pragma unroll
                for (int q = 0; q < 4; q++) acc[i][j][q] = 0.0f;

        for (int kt = 0; kt < NK; kt++) {
            asm volatile("cp.async.wait_group 0;" ::: "memory");
            __syncthreads();

            const uint32_t sb = sbase + (uint32_t)(kt & 1) * STAGEB;
            load_frags(sb, 0, 0);                 // LDSM first (results needed soonest)

            if (kt + 1 < NK) {
                load_stage(bm, bn, kt + 1, (kt + 1) & 1);
            } else if (tnext < ntiles) {
                // last K-chunk: prefetch NEXT tile's stage 0 into buf0.
                // buf0 was last read at kt=NK-2; this iteration's top sync makes the
                // overwrite WAR-safe. Latency hides under kt's MMAs + the epilogue.
                load_stage((tnext / ntn) << 7, (tnext % ntn) << 6, 0, 0);
            }

            #pragma unroll
            for (int ksi = 0; ksi < 4; ksi++) {
                const int cur = ksi & 1;
                if (ksi < 3) load_frags(sb, cur ^ 1, (ksi + 1) * 16);

                // pass-major issue, per-acc order hh -> hl -> lh (order preserved)
                #pragma unroll
                for (int mi = 0; mi < 2; mi++)
                    #pragma unroll
                    for (int nt = 0; nt < 2; nt++) {
                        mma_bf16(acc[mi][2 * nt],     ah[cur][mi], bh[cur][nt][0], bh[cur][nt][1]);
                        mma_bf16(acc[mi][2 * nt + 1], ah[cur][mi], bh[cur][nt][2], bh[cur][nt][3]);
                    }
                #pragma unroll
                for (int mi = 0; mi < 2; mi++)
                    #pragma unroll
                    for (int nt = 0; nt < 2; nt++) {
                        mma_bf16(acc[mi][2 * nt],     ah[cur][mi], bl[cur][nt][0], bl[cur][nt][1]);
                        mma_bf16(acc[mi][2 * nt + 1], ah[cur][mi], bl[cur][nt][2], bl[cur][nt][3]);
                    }
                #pragma unroll
                for (int mi = 0; mi < 2; mi++)
                    #pragma unroll
                    for (int nt = 0; nt < 2; nt++) {
                        mma_bf16(acc[mi][2 * nt],     al[cur][mi], bh[cur][nt][0], bh[cur][nt][1]);
                        mma_bf16(acc[mi][2 * nt + 1], al[cur][mi], bh[cur][nt][2], bh[cur][nt][3]);
                    }
            }
        }

        // ---------------- epilogue (register-only; overlaps next tile's loads) --------
        #pragma unroll
        for (int mi = 0; mi < 2; mi++) {
            #pragma unroll
            for (int half = 0; half < 2; half++) {
                const int row = bm + wm + mi * 16 + (lid >> 2) + half * 8;
                if (row >= M) continue;
                #pragma unroll
                for (int ni = 0; ni < 4; ni++) {
                    const int cn = bn + wn + ni * 8 + 2 * (lid & 3);
                    float x0 = acc[mi][ni][2 * half + 0];
                    float x1 = acc[mi][ni][2 * half + 1];
                    if (BIAS) { x0 += bias[cn]; x1 += bias[cn + 1]; }
                    if (RELU) { x0 = fmaxf(x0, 0.0f); x1 = fmaxf(x1, 0.0f); }
                    const size_t off = (size_t)row * N + cn;
                    if (OUTF32) {
                        *reinterpret_cast<float2*>(Cf + off) = make_float2(x0, x1);
                    } else {
                        const __nv_bfloat16 h0 = __float2bfloat16(x0);
                        const __nv_bfloat16 h1 = __float2bfloat16(x1);
                        const __nv_bfloat16 l0 = __float2bfloat16(x0 - __bfloat162float(h0));
                        const __nv_bfloat16 l1 = __float2bfloat16(x1 - __bfloat162float(h1));
                        __nv_bfloat162 th(h0, h1), tl(l0, l1);
                        *reinterpret_cast<uint32_t*>(Chi + off) = *reinterpret_cast<uint32_t*>(&th);
                        *reinterpret_cast<uint32_t*>(Clo + off) = *reinterpret_cast<uint32_t*>(&tl);
                    }
                }
            }
        }
    }
}

// ---------------- conversions ----------------
__global__ void conv_split(const float* __restrict__ X, __nv_bfloat16* __restrict__ hi,
                           __nv_bfloat16* __restrict__ lo, size_t n)
{
    const size_t i = (size_t)blockIdx.x * blockDim.x + threadIdx.x;
    if (i >= n) return;
    const float x = X[i];
    const __nv_bfloat16 h = __float2bfloat16(x);
    hi[i] = h;
    lo[i] = __float2bfloat16(x - __bfloat162float(h));
}

// W: [K,N] row-major fp32 -> B: [N,K] row-major bf16 hi/lo
__global__ void convT_split(const float* __restrict__ W, __nv_bfloat16* __restrict__ hi,
                            __nv_bfloat16* __restrict__ lo, int K, int N)
{
    const int idx = blockIdx.x * blockDim.x + threadIdx.x;
    if (idx >= K * N) return;
    const int n = idx / K;
    const int k = idx - n * K;
    const float x = W[(size_t)k * N + n];
    const __nv_bfloat16 h = __float2bfloat16(x);
    hi[idx] = h;
    lo[idx] = __float2bfloat16(x - __bfloat162float(h));
}

// -------------- gather-mean + bias + relu -> h1 hi/lo --------------
__global__ void gather_mean_relu(const int* __restrict__ faces, const float* __restrict__ b1)
{
    const int f = blockIdx.x;
    const int c = threadIdx.x;           // 128 threads -> 128 float4 = 512 floats
    const int i0 = faces[3 * f + 0];
    const int i1 = faces[3 * f + 1];
    const int i2 = faces[3 * f + 2];
    const float4 a = reinterpret_cast<const float4*>(g_Y + (size_t)i0 * DD)[c];
    const float4 b = reinterpret_cast<const float4*>(g_Y + (size_t)i1 * DD)[c];
    const float4 d = reinterpret_cast<const float4*>(g_Y + (size_t)i2 * DD)[c];
    const float4 bb = reinterpret_cast<const float4*>(b1)[c];
    const float s = 1.0f / 3.0f;
    float o[4];
    o[0] = fmaxf((a.x + b.x + d.x) * s + bb.x, 0.0f);
    o[1] = fmaxf((a.y + b.y + d.y) * s + bb.y, 0.0f);
    o[2] = fmaxf((a.z + b.z + d.z) * s + bb.z, 0.0f);
    o[3] = fmaxf((a.w + b.w + d.w) * s + bb.w, 0.0f);

    uint32_t hp[2], lp[2];
    #pragma unroll
    for (int jj = 0; jj < 2; jj++) {
        const __nv_bfloat16 ha = __float2bfloat16(o[2 * jj]);
        const __nv_bfloat16 hb = __float2bfloat16(o[2 * jj + 1]);
        const __nv_bfloat16 la = __float2bfloat16(o[2 * jj] - __bfloat162float(ha));
        const __nv_bfloat16 lb = __float2bfloat16(o[2 * jj + 1] - __bfloat162float(hb));
        __nv_bfloat162 th(ha, hb), tl(la, lb);
        hp[jj] = *reinterpret_cast<uint32_t*>(&th);
        lp[jj] = *reinterpret_cast<uint32_t*>(&tl);
    }
    const size_t off = (size_t)f * DD + c * 4;
    *reinterpret_cast<uint2*>(g_h1hi + off) = make_uint2(hp[0], hp[1]);
    *reinterpret_cast<uint2*>(g_h1lo + off) = make_uint2(lp[0], lp[1]);
}

// -------------- zero the scatter accumulators --------------
__global__ void zero_buffers()
{
    const int i = blockIdx.x * blockDim.x + threadIdx.x;
    if (i < NV * 3) g_sum[i] = 0.0f;
    if (i < NV) g_cnt[i] = 0.0f;
}

// -------------- FUSED: out12 = h3 @ W4 + b4, then procrustes + transform + scatter --------------
__global__ void __launch_bounds__(256)
tail_fused(const float* __restrict__ W4, const float* __restrict__ b4,
           const float* __restrict__ verts, const int* __restrict__ faces,
           float* __restrict__ out)
{
    __shared__ float sW[256 * 12];
    __shared__ float sb[12];
    for (int i = threadIdx.x; i < 256 * 12; i += 256) sW[i] = W4[i];
    if (threadIdx.x < 12) sb[threadIdx.x] = b4[threadIdx.x];
    __syncthreads();

    const int f = blockIdx.x * 256 + threadIdx.x;
    if (f >= NF) return;

    // ---- out12 = h3[f] @ W4 + b4 ----
    float o[12];
    #pragma unroll
    for (int j = 0; j < 12; j++) o[j] = sb[j];
    const float4* row = reinterpret_cast<const float4*>(g_h3 + (size_t)f * 256);
    #pragma unroll 4
    for (int k4 = 0; k4 < 64; k4++) {
        const float4 v = row[k4];
        const int k = k4 * 4;
        #pragma unroll
        for (int j = 0; j < 12; j++) o[j] = fmaf(v.x, sW[(k + 0) * 12 + j], o[j]);
        #pragma unroll
        for (int j = 0; j < 12; j++) o[j] = fmaf(v.y, sW[(k + 1) * 12 + j], o[j]);
        #pragma unroll
        for (int j = 0; j < 12; j++) o[j] = fmaf(v.z, sW[(k + 2) * 12 + j], o[j]);
        #pragma unroll
        for (int j = 0; j < 12; j++) o[j] = fmaf(v.w, sW[(k + 3) * 12 + j], o[j]);
    }

    const float m0 = o[0], m1 = o[1], m2 = o[2];
    const float m3 = o[3], m4 = o[4], m5 = o[5];
    const float m6 = o[6], m7 = o[7], m8 = o[8];
    const float t0 = o[9], t1 = o[10], t2 = o[11];

    // ---- Horn's 4x4 K matrix + Jacobi eigensolver ----
    float A[4][4];
    A[0][0] =  m0 + m4 + m8;
    A[1][1] =  m0 - m4 - m8;
    A[2][2] = -m0 + m4 - m8;
    A[3][3] = -m0 - m4 + m8;
    A[0][1] = A[1][0] = m7 - m5;
    A[0][2] = A[2][0] = m2 - m6;
    A[0][3] = A[3][0] = m3 - m1;
    A[1][2] = A[2][1] = m1 + m3;
    A[1][3] = A[3][1] = m2 + m6;
    A[2][3] = A[3][2] = m5 + m7;

    float V[4][4] = {{1,0,0,0},{0,1,0,0},{0,0,1,0},{0,0,0,1}};

    #pragma unroll 1
    for (int sweep = 0; sweep < 8; sweep++) {
        #pragma unroll
        for (int pi = 0; pi < 6; pi++) {
            const int p = (pi < 3) ? 0 : ((pi < 5) ? 1 : 2);
            const int q = (pi == 0) ? 1 : ((pi == 1 || pi == 3) ? 2 : 3);
            const float apq = A[p][q];
            if (fabsf(apq) < 1e-30f) continue;
            const float tau = (A[q][q] - A[p][p]) / (2.0f * apq);
            const float tt  = copysignf(1.0f, tau) / (fabsf(tau) + sqrtf(tau * tau + 1.0f));
            const float c   = rsqrtf(tt * tt + 1.0f);
            const float s   = tt * c;
            A[p][p] = A[p][p] - tt * apq;
            A[q][q] = A[q][q] + tt * apq;
            A[p][q] = A[q][p] = 0.0f;
            #pragma unroll
            for (int r = 0; r < 4; r++) {
                if (r == p || r == q) continue;
                const float arp = A[r][p], arq = A[r][q];
                A[r][p] = A[p][r] = c * arp - s * arq;
                A[r][q] = A[q][r] = s * arp + c * arq;
            }
            #pragma unroll
            for (int r = 0; r < 4; r++) {
                const float vrp = V[r][p], vrq = V[r][q];
                V[r][p] = c * vrp - s * vrq;
                V[r][q] = s * vrp + c * vrq;
            }
        }
    }

    float qw = V[0][0], qx = V[1][0], qy = V[2][0], qz = V[3][0];
    float bd = A[0][0];
    if (A[1][1] > bd) { bd = A[1][1]; qw = V[0][1]; qx = V[1][1]; qy = V[2][1]; qz = V[3][1]; }
    if (A[2][2] > bd) { bd = A[2][2]; qw = V[0][2]; qx = V[1][2]; qy = V[2][2]; qz = V[3][2]; }
    if (A[3][3] > bd) { bd = A[3][3]; qw = V[0][3]; qx = V[1][3]; qy = V[2][3]; qz = V[3][3]; }
    const float qn = rsqrtf(qw * qw + qx * qx + qy * qy + qz * qz);
    qw *= qn; qx *= qn; qy *= qn; qz *= qn;

    float R[3][3];
    R[0][0] = 1.0f - 2.0f * (qy * qy + qz * qz);
    R[0][1] = 2.0f * (qx * qy - qw * qz);
    R[0][2] = 2.0f * (qx * qz + qw * qy);
    R[1][0] = 2.0f * (qx * qy + qw * qz);
    R[1][1] = 1.0f - 2.0f * (qx * qx + qz * qz);
    R[1][2] = 2.0f * (qy * qz - qw * qx);
    R[2][0] = 2.0f * (qx * qz - qw * qy);
    R[2][1] = 2.0f * (qy * qz + qw * qx);
    R[2][2] = 1.0f - 2.0f * (qx * qx + qy * qy);

    float* ro = out + (size_t)(NV * 3) + (size_t)NF * 9 + (size_t)f * 9;
    #pragma unroll
    for (int i = 0; i < 3; i++)
        #pragma unroll
        for (int j = 0; j < 3; j++) ro[i * 3 + j] = R[i][j];

    float* tp = out + (size_t)(NV * 3) + (size_t)f * 9;
    #pragma unroll
    for (int i = 0; i < 3; i++) {
        const int vi = faces[3 * f + i];
        const float px = verts[3 * vi + 0];
        const float py = verts[3 * vi + 1];
        const float pz = verts[3 * vi + 2];
        const float ox = px * R[0][0] + py * R[1][0] + pz * R[2][0] + t0;
        const float oy = px * R[0][1] + py * R[1][1] + pz * R[2][1] + t1;
        const float oz = px * R[0][2] + py * R[1][2] + pz * R[2][2] + t2;
        tp[i * 3 + 0] = ox;
        tp[i * 3 + 1] = oy;
        tp[i * 3 + 2] = oz;
        atomicAdd(&g_sum[(size_t)vi * 3 + 0], ox);
        atomicAdd(&g_sum[(size_t)vi * 3 + 1], oy);
        atomicAdd(&g_sum[(size_t)vi * 3 + 2], oz);
        atomicAdd(&g_cnt[vi], 1.0f);
    }
}

// -------------- segment mean finalize --------------
__global__ void finalize(float* __restrict__ out)
{
    const int v = blockIdx.x * blockDim.x + threadIdx.x;
    if (v >= NV) return;
    const float c = fmaxf(g_cnt[v], 1.0f);
    out[v * 3 + 0] = g_sum[v * 3 + 0] / c;
    out[v * 3 + 1] = g_sum[v * 3 + 1] / c;
    out[v * 3 + 2] = g_sum[v * 3 + 2] / c;
}

// ---------------- host launcher ----------------
extern "C" void kernel_launch(void* const* d_in, const int* in_sizes, int n_in,
                              void* d_out, int out_size)
{
    const float* verts    = (const float*)d_in[0];
    const float* features = (const float*)d_in[1];
    const int*   faces    = (const int*)d_in[2];
    const float* W1 = (const float*)d_in[3];
    const float* b1 = (const float*)d_in[4];
    const float* W2 = (const float*)d_in[5];
    const float* b2 = (const float*)d_in[6];
    const float* W3 = (const float*)d_in[7];
    const float* b3 = (const float*)d_in[8];
    const float* W4 = (const float*)d_in[9];
    const float* b4 = (const float*)d_in[10];
    float* out = (float*)d_out;

    void *pfhi, *pflo, *pY, *ph1hi, *ph1lo, *ph2hi, *ph2lo, *ph3;
    void *pB1hi, *pB1lo, *pB2hi, *pB2lo, *pB3hi, *pB3lo;
    cudaGetSymbolAddress(&pfhi,  g_fhi);
    cudaGetSymbolAddress(&pflo,  g_flo);
    cudaGetSymbolAddress(&pY,    g_Y);
    cudaGetSymbolAddress(&ph1hi, g_h1hi);
    cudaGetSymbolAddress(&ph1lo, g_h1lo);
    cudaGetSymbolAddress(&ph2hi, g_h2hi);
    cudaGetSymbolAddress(&ph2lo, g_h2lo);
    cudaGetSymbolAddress(&ph3,   g_h3);
    cudaGetSymbolAddress(&pB1hi, g_B1hi);
    cudaGetSymbolAddress(&pB1lo, g_B1lo);
    cudaGetSymbolAddress(&pB2hi, g_B2hi);
    cudaGetSymbolAddress(&pB2lo, g_B2lo);
    cudaGetSymbolAddress(&pB3hi, g_B3hi);
    cudaGetSymbolAddress(&pB3lo, g_B3lo);

    cudaFuncSetAttribute(gemm_mma<false, false, true>,
                         cudaFuncAttributeMaxDynamicSharedMemorySize, GEMM_SMEM_BYTES);
    cudaFuncSetAttribute(gemm_mma<true, true, false>,
                         cudaFuncAttributeMaxDynamicSharedMemorySize, GEMM_SMEM_BYTES);
    cudaFuncSetAttribute(gemm_mma<true, true, true>,
                         cudaFuncAttributeMaxDynamicSharedMemorySize, GEMM_SMEM_BYTES);

    // #1: features split
    {
        const size_t nf = (size_t)NV * DD;
        conv_split<<<(unsigned)((nf + 255) / 256), 256>>>(features, (__nv_bfloat16*)pfhi,
                                                          (__nv_bfloat16*)pflo, nf);
    }
    // #2: W1 split
    convT_split<<<(DD * DD + 255) / 256, 256>>>(W1, (__nv_bfloat16*)pB1hi, (__nv_bfloat16*)pB1lo, DD, DD);

    // #3: Y = features @ W1   (M=NV, N=512, K=512) — fp32 out (persistent grid)
    gemm_mma<false, false, true><<<GEMM_GRID, 256, GEMM_SMEM_BYTES>>>(
        (const __nv_bfloat16*)pfhi, (const __nv_bfloat16*)pflo,
        (const __nv_bfloat16*)pB1hi, (const __nv_bfloat16*)pB1lo,
        nullptr, (float*)pY, nullptr, nullptr, NV, 512, 512);

    // #4: h1 = relu(mean-gather(Y) + b1) -> hi/lo   [PROFILED THIS ROUND]
    gather_mean_relu<<<NF, 128>>>(faces, b1);

    // #5: W2 split ; #6: h2 = relu(h1 @ W2 + b2) -> hi/lo
    convT_split<<<(DD * DD + 255) / 256, 256>>>(W2, (__nv_bfloat16*)pB2hi, (__nv_bfloat16*)pB2lo, DD, DD);
    gemm_mma<true, true, false><<<GEMM_GRID, 256, GEMM_SMEM_BYTES>>>(
        (const __nv_bfloat16*)ph1hi, (const __nv_bfloat16*)ph1lo,
        (const __nv_bfloat16*)pB2hi, (const __nv_bfloat16*)pB2lo,
        b2, nullptr, (__nv_bfloat16*)ph2hi, (__nv_bfloat16*)ph2lo, NF, 512, 512);

    // #7: W3 split ; #8: h3 = relu(h2 @ W3 + b3) -> fp32
    convT_split<<<(DD * 256 + 255) / 256, 256>>>(W3, (__nv_bfloat16*)pB3hi, (__nv_bfloat16*)pB3lo, DD, 256);
    gemm_mma<true, true, true><<<GEMM_GRID, 256, GEMM_SMEM_BYTES>>>(
        (const __nv_bfloat16*)ph2hi, (const __nv_bfloat16*)ph2lo,
        (const __nv_bfloat16*)pB3hi, (const __nv_bfloat16*)pB3lo,
        b3, (float*)ph3, nullptr, nullptr, NF, 256, 512);

    // #9: zero scatter accumulators ; #10: fused final_gemm + procrustes + scatter
    zero_buffers<<<(NV * 3 + 255) / 256, 256>>>();
    tail_fused<<<(NF + 255) / 256, 256>>>(W4, b4, verts, faces, out);

    // #11: segment mean
    finalize<<<(NV + 255) / 256, 256>>>(out);
}

// round 11
// speedup vs baseline: 1.0901x; 1.0901x over previous
#include <cuda_runtime.h>
#include <cuda_bf16.h>
#include <cstddef>
#include <cstdint>

#define NV 100000
#define NF 200000
#define DD 512

// ---------------- scratch (static device arrays; no allocation) ----------------
__device__ __align__(256) __nv_bfloat16 g_fhi[(size_t)NV * DD];
__device__ __align__(256) __nv_bfloat16 g_flo[(size_t)NV * DD];
__device__ __align__(256) float         g_Y[(size_t)NV * DD];
__device__ __align__(256) __nv_bfloat16 g_h1hi[(size_t)NF * DD];
__device__ __align__(256) __nv_bfloat16 g_h1lo[(size_t)NF * DD];
__device__ __align__(256) __nv_bfloat16 g_h2hi[(size_t)NF * DD];
__device__ __align__(256) __nv_bfloat16 g_h2lo[(size_t)NF * DD];
__device__ __align__(256) float         g_h3[(size_t)NF * 256];
__device__ __align__(256) __nv_bfloat16 g_B1hi[DD * DD];
__device__ __align__(256) __nv_bfloat16 g_B1lo[DD * DD];
__device__ __align__(256) __nv_bfloat16 g_B2hi[DD * DD];
__device__ __align__(256) __nv_bfloat16 g_B2lo[DD * DD];
__device__ __align__(256) __nv_bfloat16 g_B3hi[256 * DD];
__device__ __align__(256) __nv_bfloat16 g_B3lo[256 * DD];
__device__ __align__(256) float         g_sum[(size_t)NV * 3];
__device__ __align__(256) float         g_cnt[NV];

// ---------------- HMMA GEMM helpers ----------------
#define CP16(dst, src) \
    asm volatile("cp.async.cg.shared.global.L2::128B [%0], [%1], 16;" :: "r"(dst), "l"(src) : "memory")

__device__ __forceinline__ void ldm_x4(uint32_t& r0, uint32_t& r1, uint32_t& r2, uint32_t& r3,
                                       uint32_t addr) {
    asm volatile("ldmatrix.sync.aligned.m8n8.x4.shared.b16 {%0,%1,%2,%3}, [%4];"
                 : "=r"(r0), "=r"(r1), "=r"(r2), "=r"(r3) : "r"(addr));
}

__device__ __forceinline__ void mma_bf16(float* c, const uint32_t* a, uint32_t b0, uint32_t b1) {
    asm volatile("mma.sync.aligned.m16n8k16.row.col.f32.bf16.bf16.f32 "
                 "{%0,%1,%2,%3}, {%4,%5,%6,%7}, {%8,%9}, {%0,%1,%2,%3};"
                 : "+f"(c[0]), "+f"(c[1]), "+f"(c[2]), "+f"(c[3])
                 : "r"(a[0]), "r"(a[1]), "r"(a[2]), "r"(a[3]), "r"(b0), "r"(b1));
}

// SW128 swizzle: 128B rows, 16B chunk c in 0..7, slot = c ^ (row & 7).
__device__ __forceinline__ uint32_t swz128(uint32_t base, int row, int chunk) {
    return base + (uint32_t)row * 128u + (uint32_t)((chunk ^ (row & 7)) << 4);
}

// ---------------- HMMA GEMM: C = [relu]( (Ahi+Alo) @ (Bhi+Blo)^T [+bias] ) ----------------
// (R9 configuration — measured 343us on gemm1, tensor=75.9%, regs=122, 2 CTAs/SM.)
// Block tile 128x64, 256 threads = 8 warps (4 M x 2 N), warp tile 32x32.
// K-chunk 64 (128B rows, SW128 swizzle), 2-stage cp.async ring, frag double-buffer.
// Stage: Ah@0(16K), Al@16K, Bh@32K(8K), Bl@40K; stage 48KB; 2 stages 96KB => 2 CTAs/SM.
#define A_MATB 16384u
#define B_BASE 32768u
#define B_MATB 8192u
#define STAGEB 49152u
#define GEMM_SMEM_BYTES (2 * STAGEB)

template<bool RELU, bool BIAS, bool OUTF32>
__global__ void __launch_bounds__(256, 2)
gemm_mma(const __nv_bfloat16* __restrict__ Ahi, const __nv_bfloat16* __restrict__ Alo,
         const __nv_bfloat16* __restrict__ Bhi, const __nv_bfloat16* __restrict__ Blo,
         const float* __restrict__ bias,
         float* __restrict__ Cf, __nv_bfloat16* __restrict__ Chi, __nv_bfloat16* __restrict__ Clo,
         int M, int N, int K)
{
    extern __shared__ __align__(256) char smem[];
    const uint32_t sbase = (uint32_t)__cvta_generic_to_shared(smem);
    const int tid = threadIdx.x;
    const int wid = tid >> 5;
    const int lid = tid & 31;
    const int wm = (wid & 3) * 32;       // warp M offset in tile (0..96)
    const int wn = (wid >> 2) * 32;      // warp N offset in tile (0 or 32)
    const int bm = blockIdx.y * 128;
    const int bn = blockIdx.x * 64;
    const int NK = K >> 6;               // K-chunks of 64

    // ldmatrix lane-address components
    const int a_row = ((lid >> 3) & 1) * 8 + (lid & 7);
    const int a_co  = lid >> 4;
    const int b_row = (lid >> 4) * 8 + (lid & 7);
    const int b_co  = (lid >> 3) & 1;

    float acc[2][4][4];
    #pragma unroll
    for (int i = 0; i < 2; i++)
        #pragma unroll
        for (int j = 0; j < 4; j++)
            #pragma unroll
            for (int q = 0; q < 4; q++) acc[i][j][q] = 0.0f;

    auto load_stage = [&](int kt, int buf) {
        const uint32_t sb = sbase + (uint32_t)buf * STAGEB;
        const int kc = kt << 6;
        #pragma unroll
        for (int i = 0; i < 4; i++) {
            const int idx = tid + i * 256;      // 0..1023
            const int r = idx >> 3, c = idx & 7;
            int gr = bm + r; if (gr >= M) gr = M - 1;
            const size_t aoff = (size_t)gr * K + kc + c * 8;
            const uint32_t da = swz128(sb, r, c);
            CP16(da,          Ahi + aoff);
            CP16(da + A_MATB, Alo + aoff);
        }
        #pragma unroll
        for (int i = 0; i < 2; i++) {
            const int idx = tid + i * 256;      // 0..511
            const int r = idx >> 3, c = idx & 7;
            const size_t boff = (size_t)(bn + r) * K + kc + c * 8;
            const uint32_t db = swz128(sb + B_BASE, r, c);
            CP16(db,          Bhi + boff);
            CP16(db + B_MATB, Blo + boff);
        }
        asm volatile("cp.async.commit_group;" ::: "memory");
    };

    // Fragment double-buffers across ks-steps
    uint32_t ah[2][2][4], al[2][2][4], bh[2][2][4], bl[2][2][4];

    auto load_frags = [&](uint32_t sb, int slot, int ks) {
        #pragma unroll
        for (int mi = 0; mi < 2; mi++) {
            const int row = wm + mi * 16 + a_row;
            const int chunk = (ks >> 3) + a_co;
            const uint32_t ra = swz128(sb, row, chunk);
            ldm_x4(ah[slot][mi][0], ah[slot][mi][1], ah[slot][mi][2], ah[slot][mi][3], ra);
            ldm_x4(al[slot][mi][0], al[slot][mi][1], al[slot][mi][2], al[slot][mi][3], ra + A_MATB);
        }
        #pragma unroll
        for (int nt = 0; nt < 2; nt++) {
            const int row = wn + nt * 16 + b_row;
            const int chunk = (ks >> 3) + b_co;
            const uint32_t rb = swz128(sb + B_BASE, row, chunk);
            ldm_x4(bh[slot][nt][0], bh[slot][nt][1], bh[slot][nt][2], bh[slot][nt][3], rb);
            ldm_x4(bl[slot][nt][0], bl[slot][nt][1], bl[slot][nt][2], bl[slot][nt][3], rb + B_MATB);
        }
    };

    load_stage(0, 0);

    for (int kt = 0; kt < NK; kt++) {
        asm volatile("cp.async.wait_group 0;" ::: "memory");
        __syncthreads();
        if (kt + 1 < NK) load_stage(kt + 1, (kt + 1) & 1);

        const uint32_t sb = sbase + (uint32_t)(kt & 1) * STAGEB;
        load_frags(sb, 0, 0);

        #pragma unroll
        for (int ksi = 0; ksi < 4; ksi++) {
            const int cur = ksi & 1;
            if (ksi < 3) load_frags(sb, cur ^ 1, (ksi + 1) * 16);

            // pass-major issue, per-acc order hh -> hl -> lh (order preserved)
            #pragma unroll
            for (int mi = 0; mi < 2; mi++)
                #pragma unroll
                for (int nt = 0; nt < 2; nt++) {
                    mma_bf16(acc[mi][2 * nt],     ah[cur][mi], bh[cur][nt][0], bh[cur][nt][1]);
                    mma_bf16(acc[mi][2 * nt + 1], ah[cur][mi], bh[cur][nt][2], bh[cur][nt][3]);
                }
            #pragma unroll
            for (int mi = 0; mi < 2; mi++)
                #pragma unroll
                for (int nt = 0; nt < 2; nt++) {
                    mma_bf16(acc[mi][2 * nt],     ah[cur][mi], bl[cur][nt][0], bl[cur][nt][1]);
                    mma_bf16(acc[mi][2 * nt + 1], ah[cur][mi], bl[cur][nt][2], bl[cur][nt][3]);
                }
            #pragma unroll
            for (int mi = 0; mi < 2; mi++)
                #pragma unroll
                for (int nt = 0; nt < 2; nt++) {
                    mma_bf16(acc[mi][2 * nt],     al[cur][mi], bh[cur][nt][0], bh[cur][nt][1]);
                    mma_bf16(acc[mi][2 * nt + 1], al[cur][mi], bh[cur][nt][2], bh[cur][nt][3]);
                }
        }
    }

    // ---------------- epilogue ----------------
    #pragma unroll
    for (int mi = 0; mi < 2; mi++) {
        #pragma unroll
        for (int half = 0; half < 2; half++) {
            const int row = bm + wm + mi * 16 + (lid >> 2) + half * 8;
            if (row >= M) continue;
            #pragma unroll
            for (int ni = 0; ni < 4; ni++) {
                const int cn = bn + wn + ni * 8 + 2 * (lid & 3);
                float x0 = acc[mi][ni][2 * half + 0];
                float x1 = acc[mi][ni][2 * half + 1];
                if (BIAS) { x0 += bias[cn]; x1 += bias[cn + 1]; }
                if (RELU) { x0 = fmaxf(x0, 0.0f); x1 = fmaxf(x1, 0.0f); }
                const size_t off = (size_t)row * N + cn;
                if (OUTF32) {
                    *reinterpret_cast<float2*>(Cf + off) = make_float2(x0, x1);
                } else {
                    const __nv_bfloat16 h0 = __float2bfloat16(x0);
                    const __nv_bfloat16 h1 = __float2bfloat16(x1);
                    const __nv_bfloat16 l0 = __float2bfloat16(x0 - __bfloat162float(h0));
                    const __nv_bfloat16 l1 = __float2bfloat16(x1 - __bfloat162float(h1));
                    __nv_bfloat162 th(h0, h1), tl(l0, l1);
                    *reinterpret_cast<uint32_t*>(Chi + off) = *reinterpret_cast<uint32_t*>(&th);
                    *reinterpret_cast<uint32_t*>(Clo + off) = *reinterpret_cast<uint32_t*>(&tl);
                }
            }
        }
    }
}

// ---------------- fused prep: feature split + W1/W2/W3 transposed splits + zeroing -------
// Ranges (element index space):
//   [0, NV*DD)                         : features -> g_fhi/g_flo
//   [+0, DD*DD)                        : W1^T -> g_B1hi/lo
//   [+0, DD*DD)                        : W2^T -> g_B2hi/lo
//   [+0, 256*DD)                       : W3^T -> g_B3hi/lo
//   [+0, NV*3)                         : g_sum = 0   (g_cnt zeroed for idx < NV)
#define PREP_N0 ((size_t)NV * DD)
#define PREP_N1 (PREP_N0 + (size_t)DD * DD)
#define PREP_N2 (PREP_N1 + (size_t)DD * DD)
#define PREP_N3 (PREP_N2 + (size_t)256 * DD)
#define PREP_N4 (PREP_N3 + (size_t)NV * 3)

__global__ void prep_all(const float* __restrict__ features,
                         const float* __restrict__ W1, const float* __restrict__ W2,
                         const float* __restrict__ W3)
{
    const size_t i = (size_t)blockIdx.x * blockDim.x + threadIdx.x;
    if (i < PREP_N0) {
        const float x = features[i];
        const __nv_bfloat16 h = __float2bfloat16(x);
        g_fhi[i] = h;
        g_flo[i] = __float2bfloat16(x - __bfloat162float(h));
    } else if (i < PREP_N1) {
        const size_t idx = i - PREP_N0;
        const int n = (int)(idx / DD), k = (int)(idx - (size_t)n * DD);
        const float x = W1[(size_t)k * DD + n];
        const __nv_bfloat16 h = __float2bfloat16(x);
        g_B1hi[idx] = h;
        g_B1lo[idx] = __float2bfloat16(x - __bfloat162float(h));
    } else if (i < PREP_N2) {
        const size_t idx = i - PREP_N1;
        const int n = (int)(idx / DD), k = (int)(idx - (size_t)n * DD);
        const float x = W2[(size_t)k * DD + n];
        const __nv_bfloat16 h = __float2bfloat16(x);
        g_B2hi[idx] = h;
        g_B2lo[idx] = __float2bfloat16(x - __bfloat162float(h));
    } else if (i < PREP_N3) {
        const size_t idx = i - PREP_N2;
        const int n = (int)(idx / DD), k = (int)(idx - (size_t)n * DD);
        const float x = W3[(size_t)k * 256 + n];
        const __nv_bfloat16 h = __float2bfloat16(x);
        g_B3hi[idx] = h;
        g_B3lo[idx] = __float2bfloat16(x - __bfloat162float(h));
    } else if (i < PREP_N4) {
        const size_t idx = i - PREP_N3;
        g_sum[idx] = 0.0f;
        if (idx < NV) g_cnt[idx] = 0.0f;
    }
}

// -------------- gather-mean + bias + relu -> h1 hi/lo --------------
__global__ void gather_mean_relu(const int* __restrict__ faces, const float* __restrict__ b1)
{
    const int f = blockIdx.x;
    const int c = threadIdx.x;           // 128 threads -> 128 float4 = 512 floats
    const int i0 = faces[3 * f + 0];
    const int i1 = faces[3 * f + 1];
    const int i2 = faces[3 * f + 2];
    const float4 a = reinterpret_cast<const float4*>(g_Y + (size_t)i0 * DD)[c];
    const float4 b = reinterpret_cast<const float4*>(g_Y + (size_t)i1 * DD)[c];
    const float4 d = reinterpret_cast<const float4*>(g_Y + (size_t)i2 * DD)[c];
    const float4 bb = reinterpret_cast<const float4*>(b1)[c];
    const float s = 1.0f / 3.0f;
    float o[4];
    o[0] = fmaxf((a.x + b.x + d.x) * s + bb.x, 0.0f);
    o[1] = fmaxf((a.y + b.y + d.y) * s + bb.y, 0.0f);
    o[2] = fmaxf((a.z + b.z + d.z) * s + bb.z, 0.0f);
    o[3] = fmaxf((a.w + b.w + d.w) * s + bb.w, 0.0f);

    uint32_t hp[2], lp[2];
    #pragma unroll
    for (int jj = 0; jj < 2; jj++) {
        const __nv_bfloat16 ha = __float2bfloat16(o[2 * jj]);
        const __nv_bfloat16 hb = __float2bfloat16(o[2 * jj + 1]);
        const __nv_bfloat16 la = __float2bfloat16(o[2 * jj] - __bfloat162float(ha));
        const __nv_bfloat16 lb = __float2bfloat16(o[2 * jj + 1] - __bfloat162float(hb));
        __nv_bfloat162 th(ha, hb), tl(la, lb);
        hp[jj] = *reinterpret_cast<uint32_t*>(&th);
        lp[jj] = *reinterpret_cast<uint32_t*>(&tl);
    }
    const size_t off = (size_t)f * DD + c * 4;
    *reinterpret_cast<uint2*>(g_h1hi + off) = make_uint2(hp[0], hp[1]);
    *reinterpret_cast<uint2*>(g_h1lo + off) = make_uint2(lp[0], lp[1]);
}

// -------------- FUSED: out12 = h3 @ W4 + b4, then procrustes + transform + scatter --------------
__global__ void __launch_bounds__(256)
tail_fused(const float* __restrict__ W4, const float* __restrict__ b4,
           const float* __restrict__ verts, const int* __restrict__ faces,
           float* __restrict__ out)
{
    __shared__ float sW[256 * 12];
    __shared__ float sb[12];
    for (int i = threadIdx.x; i < 256 * 12; i += 256) sW[i] = W4[i];
    if (threadIdx.x < 12) sb[threadIdx.x] = b4[threadIdx.x];
    __syncthreads();

    const int f = blockIdx.x * 256 + threadIdx.x;
    if (f >= NF) return;

    // ---- out12 = h3[f] @ W4 + b4 ----
    float o[12];
    #pragma unroll
    for (int j = 0; j < 12; j++) o[j] = sb[j];
    const float4* row = reinterpret_cast<const float4*>(g_h3 + (size_t)f * 256);
    #pragma unroll 4
    for (int k4 = 0; k4 < 64; k4++) {
        const float4 v = row[k4];
        const int k = k4 * 4;
        #pragma unroll
        for (int j = 0; j < 12; j++) o[j] = fmaf(v.x, sW[(k + 0) * 12 + j], o[j]);
        #pragma unroll
        for (int j = 0; j < 12; j++) o[j] = fmaf(v.y, sW[(k + 1) * 12 + j], o[j]);
        #pragma unroll
        for (int j = 0; j < 12; j++) o[j] = fmaf(v.z, sW[(k + 2) * 12 + j], o[j]);
        #pragma unroll
        for (int j = 0; j < 12; j++) o[j] = fmaf(v.w, sW[(k + 3) * 12 + j], o[j]);
    }

    const float m0 = o[0], m1 = o[1], m2 = o[2];
    const float m3 = o[3], m4 = o[4], m5 = o[5];
    const float m6 = o[6], m7 = o[7], m8 = o[8];
    const float t0 = o[9], t1 = o[10], t2 = o[11];

    // ---- Horn's 4x4 K matrix + Jacobi eigensolver ----
    float A[4][4];
    A[0][0] =  m0 + m4 + m8;
    A[1][1] =  m0 - m4 - m8;
    A[2][2] = -m0 + m4 - m8;
    A[3][3] = -m0 - m4 + m8;
    A[0][1] = A[1][0] = m7 - m5;
    A[0][2] = A[2][0] = m2 - m6;
    A[0][3] = A[3][0] = m3 - m1;
    A[1][2] = A[2][1] = m1 + m3;
    A[1][3] = A[3][1] = m2 + m6;
    A[2][3] = A[3][2] = m5 + m7;

    float V[4][4] = {{1,0,0,0},{0,1,0,0},{0,0,1,0},{0,0,0,1}};

    #pragma unroll 1
    for (int sweep = 0; sweep < 8; sweep++) {
        #pragma unroll
        for (int pi = 0; pi < 6; pi++) {
            const int p = (pi < 3) ? 0 : ((pi < 5) ? 1 : 2);
            const int q = (pi == 0) ? 1 : ((pi == 1 || pi == 3) ? 2 : 3);
            const float apq = A[p][q];
            if (fabsf(apq) < 1e-30f) continue;
            const float tau = (A[q][q] - A[p][p]) / (2.0f * apq);
            const float tt  = copysignf(1.0f, tau) / (fabsf(tau) + sqrtf(tau * tau + 1.0f));
            const float c   = rsqrtf(tt * tt + 1.0f);
            const float s   = tt * c;
            A[p][p] = A[p][p] - tt * apq;
            A[q][q] = A[q][q] + tt * apq;
            A[p][q] = A[q][p] = 0.0f;
            #pragma unroll
            for (int r = 0; r < 4; r++) {
                if (r == p || r == q) continue;
                const float arp = A[r][p], arq = A[r][q];
                A[r][p] = A[p][r] = c * arp - s * arq;
                A[r][q] = A[q][r] = s * arp + c * arq;
            }
            #pragma unroll
            for (int r = 0; r < 4; r++) {
                const float vrp = V[r][p], vrq = V[r][q];
                V[r][p] = c * vrp - s * vrq;
                V[r][q] = s * vrp + c * vrq;
            }
        }
    }

    float qw = V[0][0], qx = V[1][0], qy = V[2][0], qz = V[3][0];
    float bd = A[0][0];
    if (A[1][1] > bd) { bd = A[1][1]; qw = V[0][1]; qx = V[1][1]; qy = V[2][1]; qz = V[3][1]; }
    if (A[2][2] > bd) { bd = A[2][2]; qw = V[0][2]; qx = V[1][2]; qy = V[2][2]; qz = V[3][2]; }
    if (A[3][3] > bd) { bd = A[3][3]; qw = V[0][3]; qx = V[1][3]; qy = V[2][3]; qz = V[3][3]; }
    const float qn = rsqrtf(qw * qw + qx * qx + qy * qy + qz * qz);
    qw *= qn; qx *= qn; qy *= qn; qz *= qn;

    float R[3][3];
    R[0][0] = 1.0f - 2.0f * (qy * qy + qz * qz);
    R[0][1] = 2.0f * (qx * qy - qw * qz);
    R[0][2] = 2.0f * (qx * qz + qw * qy);
    R[1][0] = 2.0f * (qx * qy + qw * qz);
    R[1][1] = 1.0f - 2.0f * (qx * qx + qz * qz);
    R[1][2] = 2.0f * (qy * qz - qw * qx);
    R[2][0] = 2.0f * (qx * qz - qw * qy);
    R[2][1] = 2.0f * (qy * qz + qw * qx);
    R[2][2] = 1.0f - 2.0f * (qx * qx + qy * qy);

    float* ro = out + (size_t)(NV * 3) + (size_t)NF * 9 + (size_t)f * 9;
    #pragma unroll
    for (int i = 0; i < 3; i++)
        #pragma unroll
        for (int j = 0; j < 3; j++) ro[i * 3 + j] = R[i][j];

    float* tp = out + (size_t)(NV * 3) + (size_t)f * 9;
    #pragma unroll
    for (int i = 0; i < 3; i++) {
        const int vi = faces[3 * f + i];
        const float px = verts[3 * vi + 0];
        const float py = verts[3 * vi + 1];
        const float pz = verts[3 * vi + 2];
        const float ox = px * R[0][0] + py * R[1][0] + pz * R[2][0] + t0;
        const float oy = px * R[0][1] + py * R[1][1] + pz * R[2][1] + t1;
        const float oz = px * R[0][2] + py * R[1][2] + pz * R[2][2] + t2;
        tp[i * 3 + 0] = ox;
        tp[i * 3 + 1] = oy;
        tp[i * 3 + 2] = oz;
        atomicAdd(&g_sum[(size_t)vi * 3 + 0], ox);
        atomicAdd(&g_sum[(size_t)vi * 3 + 1], oy);
        atomicAdd(&g_sum[(size_t)vi * 3 + 2], oz);
        atomicAdd(&g_cnt[vi], 1.0f);
    }
}

// -------------- segment mean finalize --------------
__global__ void finalize(float* __restrict__ out)
{
    const int v = blockIdx.x * blockDim.x + threadIdx.x;
    if (v >= NV) return;
    const float c = fmaxf(g_cnt[v], 1.0f);
    out[v * 3 + 0] = g_sum[v * 3 + 0] / c;
    out[v * 3 + 1] = g_sum[v * 3 + 1] / c;
    out[v * 3 + 2] = g_sum[v * 3 + 2] / c;
}

// ---------------- host launcher ----------------
extern "C" void kernel_launch(void* const* d_in, const int* in_sizes, int n_in,
                              void* d_out, int out_size)
{
    const float* verts    = (const float*)d_in[0];
    const float* features = (const float*)d_in[1];
    const int*   faces    = (const int*)d_in[2];
    const float* W1 = (const float*)d_in[3];
    const float* b1 = (const float*)d_in[4];
    const float* W2 = (const float*)d_in[5];
    const float* b2 = (const float*)d_in[6];
    const float* W3 = (const float*)d_in[7];
    const float* b3 = (const float*)d_in[8];
    const float* W4 = (const float*)d_in[9];
    const float* b4 = (const float*)d_in[10];
    float* out = (float*)d_out;

    void *pfhi, *pflo, *pY, *ph1hi, *ph1lo, *ph2hi, *ph2lo, *ph3;
    void *pB1hi, *pB1lo, *pB2hi, *pB2lo, *pB3hi, *pB3lo;
    cudaGetSymbolAddress(&pfhi,  g_fhi);
    cudaGetSymbolAddress(&pflo,  g_flo);
    cudaGetSymbolAddress(&pY,    g_Y);
    cudaGetSymbolAddress(&ph1hi, g_h1hi);
    cudaGetSymbolAddress(&ph1lo, g_h1lo);
    cudaGetSymbolAddress(&ph2hi, g_h2hi);
    cudaGetSymbolAddress(&ph2lo, g_h2lo);
    cudaGetSymbolAddress(&ph3,   g_h3);
    cudaGetSymbolAddress(&pB1hi, g_B1hi);
    cudaGetSymbolAddress(&pB1lo, g_B1lo);
    cudaGetSymbolAddress(&pB2hi, g_B2hi);
    cudaGetSymbolAddress(&pB2lo, g_B2lo);
    cudaGetSymbolAddress(&pB3hi, g_B3hi);
    cudaGetSymbolAddress(&pB3lo, g_B3lo);

    cudaFuncSetAttribute(gemm_mma<false, false, true>,
                         cudaFuncAttributeMaxDynamicSharedMemorySize, GEMM_SMEM_BYTES);
    cudaFuncSetAttribute(gemm_mma<true, true, false>,
                         cudaFuncAttributeMaxDynamicSharedMemorySize, GEMM_SMEM_BYTES);
    cudaFuncSetAttribute(gemm_mma<true, true, true>,
                         cudaFuncAttributeMaxDynamicSharedMemorySize, GEMM_SMEM_BYTES);

    // #1: fused prep (feature split, W1/W2/W3 splits, scatter-buffer zeroing)
    {
        const size_t total = PREP_N4;
        prep_all<<<(unsigned)((total + 255) / 256), 256>>>(features, W1, W2, W3);
    }

    // #2: Y = features @ W1   (M=NV, N=512, K=512) — fp32 out
    gemm_mma<false, false, true><<<dim3(8, (NV + 127) / 128), 256, GEMM_SMEM_BYTES>>>(
        (const __nv_bfloat16*)pfhi, (const __nv_bfloat16*)pflo,
        (const __nv_bfloat16*)pB1hi, (const __nv_bfloat16*)pB1lo,
        nullptr, (float*)pY, nullptr, nullptr, NV, 512, 512);

    // #3: h1 = relu(mean-gather(Y) + b1) -> hi/lo
    gather_mean_relu<<<NF, 128>>>(faces, b1);

    // #4: h2 = relu(h1 @ W2 + b2) -> hi/lo   [PROFILED — largest GEMM]
    gemm_mma<true, true, false><<<dim3(8, (NF + 127) / 128), 256, GEMM_SMEM_BYTES>>>(
        (const __nv_bfloat16*)ph1hi, (const __nv_bfloat16*)ph1lo,
        (const __nv_bfloat16*)pB2hi, (const __nv_bfloat16*)pB2lo,
        b2, nullptr, (__nv_bfloat16*)ph2hi, (__nv_bfloat16*)ph2lo, NF, 512, 512);

    // #5: h3 = relu(h2 @ W3 + b3) -> fp32
    gemm_mma<true, true, true><<<dim3(4, (NF + 127) / 128), 256, GEMM_SMEM_BYTES>>>(
        (const __nv_bfloat16*)ph2hi, (const __nv_bfloat16*)ph2lo,
        (const __nv_bfloat16*)pB3hi, (const __nv_bfloat16*)pB3lo,
        b3, (float*)ph3, nullptr, nullptr, NF, 256, 512);

    // #6: fused final_gemm + procrustes + scatter
    tail_fused<<<(NF + 255) / 256, 256>>>(W4, b4, verts, faces, out);

    // #7: segment mean
    finalize<<<(NV + 255) / 256, 256>>>(out);
}